// round 3
// baseline (speedup 1.0000x reference)
#include <cuda_runtime.h>
#include <math.h>

#define BSZ 1024
#define ISZ 2048
#define OSZ 1024
#define NW  32        // B/32 batch bit-words
#define SEQ 32

// ---------------- device state (all re-initialized every launch) -------------
__device__ float    g_wT[ISZ*OSZ];     // weight, [I][O] layout (transposed)
__device__ float    g_A [ISZ*OSZ];     // running A = sum d^{t-k} M_k, [I][O]
__device__ unsigned g_sb[NW*ISZ];      // input spike bits, [bg][i]
__device__ unsigned g_zb[NW*OSZ];      // output spike bits, [bg][o]
__device__ float    g_S [ISZ];         // per-input batch spike counts (float, exact ints)
__device__ float    g_vf[BSZ*OSZ];     // fallback v if out_size too small

// ---------------- K0a: build input bitmasks + column counts ------------------
__global__ void k_build_s(const float* __restrict__ s) {
    int id = blockIdx.x * blockDim.x + threadIdx.x;
    if (id >= NW * ISZ) return;
    int i  = id & (ISZ - 1);
    int bg = id >> 11;
    unsigned w = 0u;
#pragma unroll
    for (int k = 0; k < 32; k++) {
        float x = s[(bg * 32 + k) * ISZ + i];
        w |= (x != 0.0f ? 1u : 0u) << k;
    }
    g_sb[bg * ISZ + i] = w;
    atomicAdd(&g_S[i], (float)__popc(w));   // exact integer adds: order-independent
}

// ---------------- K0b: transpose weight [O][I] -> wT [I][O] ------------------
__global__ void k_wT(const float* __restrict__ w) {
    int id = blockIdx.x * blockDim.x + threadIdx.x;   // id = i*O + o
    if (id >= ISZ * OSZ) return;
    int o = id & (OSZ - 1);
    int i = id >> 10;
    g_wT[id] = w[o * ISZ + i];
}

// ---------------- K1: sparse forward GEMM + LIF + spike-bit build ------------
// grid (O/128, NW), block 128. CTA covers 32 batches x 128 outputs.
__global__ __launch_bounds__(128) void k_fwd(const float* __restrict__ bias,
                                             float* __restrict__ v,
                                             float* __restrict__ zout,
                                             float vdecay, int last) {
    __shared__ float    acc[32 * 128];
    __shared__ unsigned masks[ISZ];
    int tid = threadIdx.x;
    int bg  = blockIdx.y;
    int o   = blockIdx.x * 128 + tid;

    for (int j = tid; j < ISZ; j += 128) masks[j] = g_sb[bg * ISZ + j];
#pragma unroll
    for (int b = 0; b < 32; b++) acc[b * 128 + tid] = 0.0f;
    __syncthreads();

    const float* wc = g_wT + o;
    for (int i = 0; i < ISZ; i++) {
        unsigned m = masks[i];           // uniform across CTA -> no divergence
        if (m) {
            float wv = wc[(size_t)i * OSZ];
            do {
                int b = __ffs(m) - 1;
                acc[b * 128 + tid] += wv;
                m &= m - 1;
            } while (m);
        }
    }
    __syncthreads();

    float bi = bias[o];
    unsigned zw = 0u;
#pragma unroll
    for (int b = 0; b < 32; b++) {
        int idx = (bg * 32 + b) * OSZ + o;
        float vv = v[idx] * vdecay + acc[b * 128 + tid] + bi;
        int sp = (vv >= 1.0f);
        if (last) zout[idx] = sp ? 1.0f : 0.0f;
        v[idx] = sp ? 0.0f : vv;          // v*(1-z) exactly
        zw |= ((unsigned)sp) << b;
    }
    g_zb[bg * OSZ + o] = zw;
}

// ---------------- K2: M = z^T s (popcount) fused with A and w update ---------
// grid (O/128, I/64), block 128. Thread owns one o, loops 64 i's.
__global__ __launch_bounds__(128) void k_upd(float a_t, float b_t, float c_t,
                                             float dpost, float etap, float etam) {
    __shared__ unsigned swt[NW * 64];   // [w][i_local]
    __shared__ float    Ssh[64];
    int tid = threadIdx.x;
    int o   = blockIdx.x * 128 + tid;
    int i0  = blockIdx.y * 64;

    for (int j = tid; j < NW * 64; j += 128) {
        int w = j >> 6, il = j & 63;
        swt[j] = g_sb[w * ISZ + i0 + il];
    }
    if (tid < 64) Ssh[tid] = g_S[i0 + tid];

    unsigned zw[NW];
    int zc = 0;
#pragma unroll
    for (int w = 0; w < NW; w++) { zw[w] = g_zb[w * OSZ + o]; zc += __popc(zw[w]); }
    float Zf = (float)zc;
    __syncthreads();

    for (int il = 0; il < 64; il++) {
        int cnt = 0;
#pragma unroll
        for (int w = 0; w < NW; w++) cnt += __popc(swt[w * 64 + il] & zw[w]);
        float m  = (float)cnt;                 // exact
        int idx  = (i0 + il) * OSZ + o;
        float An = g_A[idx] * dpost + m;       // A_t = d*A_{t-1} + M_t
        g_A[idx] = An;
        float e1 = a_t * Zf + b_t * m;         // eta+ term: z^T tpre
        float e2 = c_t * Ssh[il] + An;         // eta- term: tpost^T s
        float wv = g_wT[idx] + (etap * e1 - etam * e2);
        wv = fminf(fmaxf(wv, -1.0f), 1.0f);
        g_wT[idx] = wv;
    }
}

// ---------------- K3: final transpose wT -> output [O][I] --------------------
__global__ void k_wout(float* __restrict__ out) {
    int id = blockIdx.x * blockDim.x + threadIdx.x;   // id = o*I + i
    if (id >= ISZ * OSZ) return;
    int i = id & (ISZ - 1);
    int o = id >> 11;
    out[id] = g_wT[(size_t)i * OSZ + o];
}

// -----------------------------------------------------------------------------
extern "C" void kernel_launch(void* const* d_in, const int* in_sizes, int n_in,
                              void* d_out, int out_size) {
    const float* s    = (const float*)d_in[0];   // input_spikes [B,I]
    const float* w    = (const float*)d_in[1];   // weight [O,I]
    const float* bias = (const float*)d_in[2];   // bias [O]
    float* out  = (float*)d_out;
    float* zout = out;

    void *pA = nullptr, *pS = nullptr, *pV = nullptr;
    cudaGetSymbolAddress(&pA, g_A);
    cudaGetSymbolAddress(&pS, g_S);
    cudaGetSymbolAddress(&pV, g_vf);

    float* v = (out_size >= 2 * BSZ * OSZ) ? (out + BSZ * OSZ) : (float*)pV;

    // per-launch state init (graph-replayed every run -> deterministic)
    cudaMemsetAsync(pA, 0, (size_t)ISZ * OSZ * sizeof(float));
    cudaMemsetAsync(pS, 0, (size_t)ISZ * sizeof(float));
    cudaMemsetAsync(v,  0, (size_t)BSZ * OSZ * sizeof(float));

    k_build_s<<<(NW * ISZ) / 256, 256>>>(s);
    k_wT<<<(ISZ * OSZ) / 256, 256>>>(w);

    // fp32-iterated trace constants, matching the reference's iterative decay
    const float d = (float)exp(-0.05);   // decay_pre = decay_post = v_decay
    float p0 = 1.0f, p1 = 1.0f;
    for (int t = 0; t < SEQ; t++) {
        p0 = p0 * d;                 // tpre/tpost trajectory for s=0 (= d^t, fp32)
        p1 = p1 * d + 1.0f;          // tpre trajectory for s=1
        k_fwd<<<dim3(OSZ / 128, NW), 128>>>(bias, v, zout, d, t == SEQ - 1);
        k_upd<<<dim3(OSZ / 128, ISZ / 64), 128>>>(p0, p1 - p0, p0, d, 1e-3f, 1e-3f);
    }

    if (out_size >= 2 * BSZ * OSZ + ISZ * OSZ)
        k_wout<<<(ISZ * OSZ) / 256, 256>>>(out + 2 * BSZ * OSZ);
}

// round 4
// speedup vs baseline: 2.9851x; 2.9851x over previous
#include <cuda_runtime.h>
#include <math.h>

#define BSZ 1024
#define ISZ 2048
#define OSZ 1024
#define NW  32        // B/32 batch bit-words
#define SEQ 32

// ---------------- device state (all re-initialized every launch) -------------
__device__ float    g_wT[ISZ*OSZ];     // weight, [I][O] layout (transposed)
__device__ float    g_A [ISZ*OSZ];     // running A = sum d^{t-k} M_k, [I][O]
__device__ unsigned g_sb[NW*ISZ];      // input spike bits, [bg][i]
__device__ unsigned g_zb[NW*OSZ];      // output spike bits, [bg][o]
__device__ float    g_S [ISZ];         // per-input batch spike counts (float, exact ints)
__device__ float    g_vf[BSZ*OSZ];     // fallback v if out_size too small

// ---------------- K0a: build input bitmasks + column counts ------------------
__global__ void k_build_s(const float* __restrict__ s) {
    int id = blockIdx.x * blockDim.x + threadIdx.x;
    if (id >= NW * ISZ) return;
    int i  = id & (ISZ - 1);
    int bg = id >> 11;
    unsigned w = 0u;
#pragma unroll
    for (int k = 0; k < 32; k++) {
        float x = s[(bg * 32 + k) * ISZ + i];
        w |= (x != 0.0f ? 1u : 0u) << k;
    }
    g_sb[bg * ISZ + i] = w;
    atomicAdd(&g_S[i], (float)__popc(w));   // exact integer adds: order-independent
}

// ---------------- K0b: tiled transpose weight [O][I] -> wT [I][O] ------------
__global__ __launch_bounds__(256) void k_wT(const float* __restrict__ w) {
    __shared__ float tile[32][33];
    int tx = threadIdx.x, ty = threadIdx.y;           // block (32, 8)
    int x = blockIdx.x * 32 + tx;                     // i (column of w)
    int y = blockIdx.y * 32 + ty;                     // o (row of w)
#pragma unroll
    for (int j = 0; j < 32; j += 8)
        tile[ty + j][tx] = w[(size_t)(y + j) * ISZ + x];
    __syncthreads();
    int xo = blockIdx.y * 32 + tx;                    // o
    int yi = blockIdx.x * 32 + ty;                    // i
#pragma unroll
    for (int j = 0; j < 32; j += 8)
        g_wT[(size_t)(yi + j) * OSZ + xo] = tile[tx][ty + j];
}

// ---------------- K1: sparse forward GEMM + LIF + spike-bit build ------------
// grid (O/64, NW), block (64, 8). Each CTA: 64 outputs x 32 batches.
// The i-dimension is split into 8 chunks of 256, one per threadIdx.y, each with
// a private smem accumulator slab -> 8 independent serial chains per thread
// column, 16 warps/CTA for occupancy. Deterministic chunk-tree reduce at end.
__global__ __launch_bounds__(512) void k_fwd(const float* __restrict__ bias,
                                             float* __restrict__ v,
                                             float* __restrict__ zout,
                                             float vdecay, int last) {
    extern __shared__ char smem_raw[];
    float*    acc   = (float*)smem_raw;                       // 8 * 32 * 64 floats
    unsigned* masks = (unsigned*)(smem_raw + 65536);          // 2048 words
    unsigned* zsh   = (unsigned*)(smem_raw + 65536 + 8192);   // 64 words

    int tid = threadIdx.x;            // 0..63  (output lane)
    int ch  = threadIdx.y;            // 0..7   (i-chunk)
    int t   = ch * 64 + tid;
    int bg  = blockIdx.y;
    int o   = blockIdx.x * 64 + tid;

    for (int j = t; j < ISZ; j += 512) masks[j] = g_sb[bg * ISZ + j];
    for (int j = tid; j < 32 * 64; j += 64) acc[ch * 2048 + j] = 0.0f;
    if (t < 64) zsh[t] = 0u;
    __syncthreads();

    const float* wc = g_wT + o;
    float* ac = acc + ch * 2048 + tid;
    for (int i = ch * 256, e = ch * 256 + 256; i < e; i++) {
        unsigned m = masks[i];        // uniform across the warp -> no divergence
        if (m) {
            float wv = wc[(size_t)i * OSZ];
            do {
                int b = __ffs(m) - 1;
                ac[b * 64] += wv;
                m &= m - 1;
            } while (m);
        }
    }
    __syncthreads();

    float bi = bias[o];
#pragma unroll
    for (int bb = 0; bb < 4; bb++) {
        int b = (ch << 2) | bb;
        float sum = 0.0f;
#pragma unroll
        for (int c = 0; c < 8; c++) sum += acc[c * 2048 + b * 64 + tid];
        int idx = (bg * 32 + b) * OSZ + o;
        float vv = v[idx] * vdecay + sum + bi;
        bool sp = (vv >= 1.0f);
        if (last) zout[idx] = sp ? 1.0f : 0.0f;
        v[idx] = sp ? 0.0f : vv;          // v*(1-z) exactly
        if (sp) atomicOr(&zsh[tid], 1u << b);   // OR: order-independent
    }
    __syncthreads();
    if (t < 64) g_zb[bg * OSZ + blockIdx.x * 64 + t] = zsh[t];
}

// ---------------- K2: M = z^T s (popcount) fused with A and w update ---------
// grid (O/128, I/16), block 128. Thread owns one o, loops 16 i's.
__global__ __launch_bounds__(128) void k_upd(float a_t, float b_t, float c_t,
                                             float dpost, float etap, float etam) {
    __shared__ unsigned swt[NW * 16];   // [w][i_local]
    __shared__ float    Ssh[16];
    int tid = threadIdx.x;
    int o   = blockIdx.x * 128 + tid;
    int i0  = blockIdx.y * 16;

    for (int j = tid; j < NW * 16; j += 128) {
        int w = j >> 4, il = j & 15;
        swt[j] = g_sb[w * ISZ + i0 + il];
    }
    if (tid < 16) Ssh[tid] = g_S[i0 + tid];

    unsigned zw[NW];
    int zc = 0;
#pragma unroll
    for (int w = 0; w < NW; w++) { zw[w] = g_zb[w * OSZ + o]; zc += __popc(zw[w]); }
    float Zf = (float)zc;
    __syncthreads();

#pragma unroll 4
    for (int il = 0; il < 16; il++) {
        int cnt = 0;
#pragma unroll
        for (int w = 0; w < NW; w++) cnt += __popc(swt[w * 16 + il] & zw[w]);
        float m  = (float)cnt;                 // exact
        int idx  = (i0 + il) * OSZ + o;
        float An = g_A[idx] * dpost + m;       // A_t = d*A_{t-1} + M_t
        g_A[idx] = An;
        float e1 = a_t * Zf + b_t * m;         // eta+ term: z^T tpre
        float e2 = c_t * Ssh[il] + An;         // eta- term: tpost^T s
        float wv = g_wT[idx] + (etap * e1 - etam * e2);
        wv = fminf(fmaxf(wv, -1.0f), 1.0f);
        g_wT[idx] = wv;
    }
}

// ---------------- K3: tiled transpose wT [I][O] -> output [O][I] --------------
__global__ __launch_bounds__(256) void k_wout(float* __restrict__ out) {
    __shared__ float tile[32][33];
    int tx = threadIdx.x, ty = threadIdx.y;           // block (32, 8)
    int x = blockIdx.x * 32 + tx;                     // o (column of wT)
    int y = blockIdx.y * 32 + ty;                     // i (row of wT)
#pragma unroll
    for (int j = 0; j < 32; j += 8)
        tile[ty + j][tx] = g_wT[(size_t)(y + j) * OSZ + x];
    __syncthreads();
    int xi = blockIdx.y * 32 + tx;                    // i
    int yo = blockIdx.x * 32 + ty;                    // o
#pragma unroll
    for (int j = 0; j < 32; j += 8)
        out[(size_t)(yo + j) * ISZ + xi] = tile[tx][ty + j];
}

// -----------------------------------------------------------------------------
extern "C" void kernel_launch(void* const* d_in, const int* in_sizes, int n_in,
                              void* d_out, int out_size) {
    const float* s    = (const float*)d_in[0];   // input_spikes [B,I]
    const float* w    = (const float*)d_in[1];   // weight [O,I]
    const float* bias = (const float*)d_in[2];   // bias [O]
    float* out  = (float*)d_out;
    float* zout = out;

    void *pA = nullptr, *pS = nullptr, *pV = nullptr;
    cudaGetSymbolAddress(&pA, g_A);
    cudaGetSymbolAddress(&pS, g_S);
    cudaGetSymbolAddress(&pV, g_vf);

    float* v = (out_size >= 2 * BSZ * OSZ) ? (out + BSZ * OSZ) : (float*)pV;

    // k_fwd needs 72.25 KB dynamic smem (acc slabs + masks + spike bits)
    const int FWD_SMEM = 65536 + 8192 + 256;
    cudaFuncSetAttribute(k_fwd, cudaFuncAttributeMaxDynamicSharedMemorySize, FWD_SMEM);

    // per-launch state init (graph-replayed every run -> deterministic)
    cudaMemsetAsync(pA, 0, (size_t)ISZ * OSZ * sizeof(float));
    cudaMemsetAsync(pS, 0, (size_t)ISZ * sizeof(float));
    cudaMemsetAsync(v,  0, (size_t)BSZ * OSZ * sizeof(float));

    k_build_s<<<(NW * ISZ) / 256, 256>>>(s);
    k_wT<<<dim3(ISZ / 32, OSZ / 32), dim3(32, 8)>>>(w);

    // fp32-iterated trace constants, matching the reference's iterative decay
    const float d = (float)exp(-0.05);   // decay_pre = decay_post = v_decay
    float p0 = 1.0f, p1 = 1.0f;
    for (int t = 0; t < SEQ; t++) {
        p0 = p0 * d;                 // tpre/tpost trajectory for s=0 (= d^t, fp32)
        p1 = p1 * d + 1.0f;          // tpre trajectory for s=1
        k_fwd<<<dim3(OSZ / 64, NW), dim3(64, 8), FWD_SMEM>>>(bias, v, zout, d, t == SEQ - 1);
        k_upd<<<dim3(OSZ / 128, ISZ / 16), 128>>>(p0, p1 - p0, p0, d, 1e-3f, 1e-3f);
    }

    if (out_size >= 2 * BSZ * OSZ + ISZ * OSZ)
        k_wout<<<dim3(OSZ / 32, ISZ / 32), dim3(32, 8)>>>(out + 2 * BSZ * OSZ);
}

// round 9
// speedup vs baseline: 4.6548x; 1.5593x over previous
#include <cuda_runtime.h>
#include <math.h>

#define BSZ 1024
#define ISZ 2048
#define OSZ 1024
#define NW  32        // B/32 batch bit-words
#define SEQ 32

// ---------------- device state (all re-initialized every launch) -------------
__device__ float    g_wT[ISZ*OSZ];     // weight, [I][O] layout (transposed)
__device__ float    g_A [ISZ*OSZ];     // running A = sum d^{t-k} M_k, [I][O]
__device__ unsigned g_sb[NW*ISZ];      // input spike bits, [bg][i]
__device__ unsigned g_zb[NW*OSZ];      // output spike bits, [bg][o]
__device__ float    g_S [ISZ];         // per-input batch spike counts (float, exact ints)
__device__ float    g_vf[BSZ*OSZ];     // fallback v if out_size too small

// ---------------- K0a: build input bitmasks + column counts ------------------
__global__ void k_build_s(const float* __restrict__ s) {
    int id = blockIdx.x * blockDim.x + threadIdx.x;
    if (id >= NW * ISZ) return;
    int i  = id & (ISZ - 1);
    int bg = id >> 11;
    unsigned w = 0u;
#pragma unroll
    for (int k = 0; k < 32; k++) {
        float x = s[(bg * 32 + k) * ISZ + i];
        w |= (x != 0.0f ? 1u : 0u) << k;
    }
    g_sb[bg * ISZ + i] = w;
    atomicAdd(&g_S[i], (float)__popc(w));   // exact integer adds: order-independent
}

// ---------------- K0b: tiled transpose weight [O][I] -> wT [I][O] ------------
__global__ __launch_bounds__(256) void k_wT(const float* __restrict__ w) {
    __shared__ float tile[32][33];
    int tx = threadIdx.x, ty = threadIdx.y;           // block (32, 8)
    int x = blockIdx.x * 32 + tx;                     // i (column of w)
    int y = blockIdx.y * 32 + ty;                     // o (row of w)
#pragma unroll
    for (int j = 0; j < 32; j += 8)
        tile[ty + j][tx] = w[(size_t)(y + j) * ISZ + x];
    __syncthreads();
    int xo = blockIdx.y * 32 + tx;                    // o
    int yi = blockIdx.x * 32 + ty;                    // i
#pragma unroll
    for (int j = 0; j < 32; j += 8)
        g_wT[(size_t)(yi + j) * OSZ + xo] = tile[tx][ty + j];
}

// ---------------- K1: sparse forward GEMM + LIF + spike-bit build ------------
// grid (O/64, NW), block (64, 8). Each CTA: 64 outputs x 32 batches.
// i split into 8 chunks of 256 (one per threadIdx.y) with private smem acc
// slabs; deterministic chunk-tree reduce. Inner loop unrolled x8 with
// predicated weight loads issued ahead of the ffs/accumulate blocks (MLP=8).
__global__ __launch_bounds__(512) void k_fwd(const float* __restrict__ bias,
                                             float* __restrict__ v,
                                             float* __restrict__ zout,
                                             float vdecay, int last) {
    extern __shared__ char smem_raw[];
    float*    acc   = (float*)smem_raw;                       // 8 * 32 * 64 floats
    unsigned* masks = (unsigned*)(smem_raw + 65536);          // 2048 words
    unsigned* zsh   = (unsigned*)(smem_raw + 65536 + 8192);   // 64 words

    int tid = threadIdx.x;            // 0..63  (output lane)
    int ch  = threadIdx.y;            // 0..7   (i-chunk)
    int t   = ch * 64 + tid;
    int bg  = blockIdx.y;
    int o   = blockIdx.x * 64 + tid;

    for (int j = t; j < ISZ; j += 512) masks[j] = g_sb[bg * ISZ + j];
    for (int j = tid; j < 32 * 64; j += 64) acc[ch * 2048 + j] = 0.0f;
    if (t < 64) zsh[t] = 0u;
    __syncthreads();

    const float* wc = g_wT + o;
    float* ac = acc + ch * 2048 + tid;

#define FWD_ACCUM(mk, wk)                                   \
    if (mk) {                                               \
        unsigned m_ = (mk);                                 \
        do {                                                \
            int b_ = __ffs(m_) - 1;                         \
            ac[b_ * 64] += (wk);                            \
            m_ &= m_ - 1;                                   \
        } while (m_);                                       \
    }

    int ibase = ch * 256;
    for (int g = 0; g < 32; g++) {
        int i = ibase + g * 8;
        uint4 ma = *(const uint4*)&masks[i];
        uint4 mb = *(const uint4*)&masks[i + 4];
        // predicated loads: all 8 issued before any accumulation -> MLP=8,
        // masked-off lanes generate no traffic
        float w0 = ma.x ? __ldg(wc + (i + 0) * OSZ) : 0.0f;
        float w1 = ma.y ? __ldg(wc + (i + 1) * OSZ) : 0.0f;
        float w2 = ma.z ? __ldg(wc + (i + 2) * OSZ) : 0.0f;
        float w3 = ma.w ? __ldg(wc + (i + 3) * OSZ) : 0.0f;
        float w4 = mb.x ? __ldg(wc + (i + 4) * OSZ) : 0.0f;
        float w5 = mb.y ? __ldg(wc + (i + 5) * OSZ) : 0.0f;
        float w6 = mb.z ? __ldg(wc + (i + 6) * OSZ) : 0.0f;
        float w7 = mb.w ? __ldg(wc + (i + 7) * OSZ) : 0.0f;
        FWD_ACCUM(ma.x, w0); FWD_ACCUM(ma.y, w1);
        FWD_ACCUM(ma.z, w2); FWD_ACCUM(ma.w, w3);
        FWD_ACCUM(mb.x, w4); FWD_ACCUM(mb.y, w5);
        FWD_ACCUM(mb.z, w6); FWD_ACCUM(mb.w, w7);
    }
#undef FWD_ACCUM
    __syncthreads();

    float bi = bias[o];
#pragma unroll
    for (int bb = 0; bb < 4; bb++) {
        int b = (ch << 2) | bb;
        float sum = 0.0f;
#pragma unroll
        for (int c = 0; c < 8; c++) sum += acc[c * 2048 + b * 64 + tid];
        int idx = (bg * 32 + b) * OSZ + o;
        float vv = v[idx] * vdecay + sum + bi;
        bool sp = (vv >= 1.0f);
        if (last) zout[idx] = sp ? 1.0f : 0.0f;
        v[idx] = sp ? 0.0f : vv;          // v*(1-z) exactly
        if (sp) atomicOr(&zsh[tid], 1u << b);   // OR: order-independent
    }
    __syncthreads();
    if (t < 64) g_zb[bg * OSZ + blockIdx.x * 64 + t] = zsh[t];
}

// ---------------- K2: M = z^T s (popcount) fused with A and w update ---------
// grid (O/128, I/16), block 128. Thread owns one o.
// w (batch word) is the OUTER loop; cnt[16] register accumulators give 16
// independent dependency chains; regs ~45 -> high occupancy.
__global__ __launch_bounds__(128) void k_upd(float a_t, float b_t, float c_t,
                                             float dpost, float etap, float etam) {
    __shared__ unsigned swt[NW * 17];   // [w][il], padded vs bank conflicts
    __shared__ float    Ssh[16];
    int tid = threadIdx.x;
    int o   = blockIdx.x * 128 + tid;
    int i0  = blockIdx.y * 16;

    for (int j = tid; j < NW * 16; j += 128) {
        int w = j >> 4, il = j & 15;
        swt[w * 17 + il] = g_sb[w * ISZ + i0 + il];
    }
    if (tid < 16) Ssh[tid] = g_S[i0 + tid];
    __syncthreads();

    int cnt[16];
#pragma unroll
    for (int il = 0; il < 16; il++) cnt[il] = 0;
    int zc = 0;

#pragma unroll 4
    for (int w = 0; w < NW; w++) {
        unsigned z = __ldg(&g_zb[w * OSZ + o]);
        zc += __popc(z);
#pragma unroll
        for (int il = 0; il < 16; il++)
            cnt[il] += __popc(swt[w * 17 + il] & z);
    }
    float Zf = (float)zc;

#pragma unroll 4
    for (int il = 0; il < 16; il++) {
        float m  = (float)cnt[il];             // exact
        int idx  = (i0 + il) * OSZ + o;
        float An = g_A[idx] * dpost + m;       // A_t = d*A_{t-1} + M_t
        g_A[idx] = An;
        float e1 = a_t * Zf + b_t * m;         // eta+ term: z^T tpre
        float e2 = c_t * Ssh[il] + An;         // eta- term: tpost^T s
        float wv = g_wT[idx] + (etap * e1 - etam * e2);
        wv = fminf(fmaxf(wv, -1.0f), 1.0f);
        g_wT[idx] = wv;
    }
}

// ---------------- K3: tiled transpose wT [I][O] -> output [O][I] --------------
__global__ __launch_bounds__(256) void k_wout(float* __restrict__ out) {
    __shared__ float tile[32][33];
    int tx = threadIdx.x, ty = threadIdx.y;           // block (32, 8)
    int x = blockIdx.x * 32 + tx;                     // o (column of wT)
    int y = blockIdx.y * 32 + ty;                     // i (row of wT)
#pragma unroll
    for (int j = 0; j < 32; j += 8)
        tile[ty + j][tx] = g_wT[(size_t)(y + j) * OSZ + x];
    __syncthreads();
    int xi = blockIdx.y * 32 + tx;                    // i
    int yo = blockIdx.x * 32 + ty;                    // o
#pragma unroll
    for (int j = 0; j < 32; j += 8)
        out[(size_t)(yo + j) * ISZ + xi] = tile[tx][ty + j];
}

// -----------------------------------------------------------------------------
extern "C" void kernel_launch(void* const* d_in, const int* in_sizes, int n_in,
                              void* d_out, int out_size) {
    const float* s    = (const float*)d_in[0];   // input_spikes [B,I]
    const float* w    = (const float*)d_in[1];   // weight [O,I]
    const float* bias = (const float*)d_in[2];   // bias [O]
    float* out  = (float*)d_out;
    float* zout = out;

    void *pA = nullptr, *pS = nullptr, *pV = nullptr;
    cudaGetSymbolAddress(&pA, g_A);
    cudaGetSymbolAddress(&pS, g_S);
    cudaGetSymbolAddress(&pV, g_vf);

    float* v = (out_size >= 2 * BSZ * OSZ) ? (out + BSZ * OSZ) : (float*)pV;

    // k_fwd needs 72.25 KB dynamic smem (acc slabs + masks + spike bits)
    const int FWD_SMEM = 65536 + 8192 + 256;
    cudaFuncSetAttribute(k_fwd, cudaFuncAttributeMaxDynamicSharedMemorySize, FWD_SMEM);

    // per-launch state init (graph-replayed every run -> deterministic)
    cudaMemsetAsync(pA, 0, (size_t)ISZ * OSZ * sizeof(float));
    cudaMemsetAsync(pS, 0, (size_t)ISZ * sizeof(float));
    cudaMemsetAsync(v,  0, (size_t)BSZ * OSZ * sizeof(float));

    k_build_s<<<(NW * ISZ) / 256, 256>>>(s);
    k_wT<<<dim3(ISZ / 32, OSZ / 32), dim3(32, 8)>>>(w);

    // fp32-iterated trace constants, matching the reference's iterative decay
    const float d = (float)exp(-0.05);   // decay_pre = decay_post = v_decay
    float p0 = 1.0f, p1 = 1.0f;
    for (int t = 0; t < SEQ; t++) {
        p0 = p0 * d;                 // tpre/tpost trajectory for s=0 (= d^t, fp32)
        p1 = p1 * d + 1.0f;          // tpre trajectory for s=1
        k_fwd<<<dim3(OSZ / 64, NW), dim3(64, 8), FWD_SMEM>>>(bias, v, zout, d, t == SEQ - 1);
        k_upd<<<dim3(OSZ / 128, ISZ / 16), 128>>>(p0, p1 - p0, p0, d, 1e-3f, 1e-3f);
    }

    if (out_size >= 2 * BSZ * OSZ + ISZ * OSZ)
        k_wout<<<dim3(OSZ / 32, ISZ / 32), dim3(32, 8)>>>(out + 2 * BSZ * OSZ);
}